// round 2
// baseline (speedup 1.0000x reference)
#include <cuda_runtime.h>

// Semantics (reference dead-code eliminated):
//   r  = eye(3); tb = -mean(mkpts0, axis=1)   // mkpts0 is [3, N] row-major
// Output: 9 floats r row-major, then 3 floats tb.
// Strategy: one float4 load per thread across 48 CTAs (full-chip MLP),
// block reduction + global float atomics, last-block finalize + scratch reset
// (graph-replay safe).

#define TPB 128

__device__ float g_sums[3];          // zero-initialized at module load
__device__ unsigned int g_count;     // zero-initialized

__global__ void svdhead_reduce(const float* __restrict__ mkpts0,
                               int n, int nblocks,
                               float* __restrict__ out, int out_size) {
    __shared__ float sh[3];
    __shared__ bool is_last;

    int tid = threadIdx.x;
    if (tid < 3) sh[tid] = 0.f;
    __syncthreads();

    // total float4 elements = 3*n/4 (n multiple of 4 assumed; true for N=8192)
    int total4 = (3 * n) >> 2;
    float acc[3] = {0.f, 0.f, 0.f};
    for (int g = blockIdx.x * TPB + tid; g < total4; g += nblocks * TPB) {
        float4 v = reinterpret_cast<const float4*>(mkpts0)[g];
        int row = (g << 2) / n;                    // all 4 lanes same row (n%4==0)
        acc[row] += (v.x + v.y) + (v.z + v.w);
    }

    // warp-level reduce each accumulator, then shared atomics (few per block)
    #pragma unroll
    for (int r = 0; r < 3; r++) {
        float s = acc[r];
        #pragma unroll
        for (int off = 16; off > 0; off >>= 1)
            s += __shfl_down_sync(0xFFFFFFFFu, s, off);
        if ((tid & 31) == 0 && s != 0.f) atomicAdd(&sh[r], s);
    }
    __syncthreads();

    if (tid < 3 && sh[tid] != 0.f) atomicAdd(&g_sums[tid], sh[tid]);
    __threadfence();

    if (tid == 0) {
        unsigned int ticket = atomicAdd(&g_count, 1u);
        is_last = (ticket == (unsigned int)nblocks - 1u);
    }
    __syncthreads();

    if (is_last && tid == 0) {
        float s0 = g_sums[0], s1 = g_sums[1], s2 = g_sums[2];
        // reset scratch for the next graph replay
        g_sums[0] = 0.f; g_sums[1] = 0.f; g_sums[2] = 0.f;
        g_count = 0u;
        __threadfence();

        float inv_n = 1.0f / (float)n;
        if (out_size >= 12) {
            out[0] = 1.f; out[1] = 0.f; out[2] = 0.f;
            out[3] = 0.f; out[4] = 1.f; out[5] = 0.f;
            out[6] = 0.f; out[7] = 0.f; out[8] = 1.f;
            out[9]  = -s0 * inv_n;
            out[10] = -s1 * inv_n;
            out[11] = -s2 * inv_n;
        }
        for (int i = 12; i < out_size; i++) out[i] = 0.f;
    }
}

extern "C" void kernel_launch(void* const* d_in, const int* in_sizes, int n_in,
                              void* d_out, int out_size) {
    const float* mkpts0 = (const float*)d_in[0];
    int n = in_sizes[0] / 3;          // [3, N]
    float* out = (float*)d_out;
    // one float4 per thread when n=8192: 6144 float4 / 128 = 48 blocks
    int total4 = (3 * n) >> 2;
    int nblocks = (total4 + TPB - 1) / TPB;
    if (nblocks > 148) nblocks = 148;
    if (nblocks < 1) nblocks = 1;
    svdhead_reduce<<<nblocks, TPB>>>(mkpts0, n, nblocks, out, out_size);
}

// round 3
// speedup vs baseline: 1.3029x; 1.3029x over previous
#include <cuda_runtime.h>

// Semantics (reference dead-code eliminated):
//   r  = eye(3); tb = -mean(mkpts0, axis=1)   // mkpts0 is [3, N] row-major
// Output: 9 floats r (row-major identity) then 3 floats tb. 12 floats total.
//
// Single-CTA latency-optimized: 1024 threads, 6 float4 loads/thread fully
// unrolled (one exposed L2-latency window), shuffle-tree reduce, warp 1
// writes the constant identity block off the critical path.

#define NTHREADS 1024

__global__ void __launch_bounds__(NTHREADS, 1)
svdhead_kernel(const float* __restrict__ mkpts0,
               int n, float* __restrict__ out, int out_size) {
    __shared__ float red[3][32];

    int tid  = threadIdx.x;
    int lane = tid & 31;
    int warp = tid >> 5;

    // Constant part of output: written immediately by warp 1 (not on the
    // reduction critical path).
    if (warp == 1) {
        if (lane < 9 && out_size >= 9)
            out[lane] = (lane == 0 || lane == 4 || lane == 8) ? 1.f : 0.f;
        // defensive tail clear for any extra poisoned elements
        for (int i = 12 + lane; i < out_size; i += 32) out[i] = 0.f;
    }

    int nf4 = n >> 2;  // float4s per row (2048 for N=8192)
    const float4* p0 = reinterpret_cast<const float4*>(mkpts0);
    const float4* p1 = p0 + nf4;
    const float4* p2 = p1 + nf4;

    float s0 = 0.f, s1 = 0.f, s2 = 0.f;
    // nf4 = 2048, NTHREADS = 1024 -> exactly 2 iterations per row; keep the
    // loop generic but it fully unrolls for the fixed shape.
    for (int j = tid; j < nf4; j += NTHREADS) {
        float4 a = p0[j];
        float4 b = p1[j];
        float4 c = p2[j];
        s0 += (a.x + a.y) + (a.z + a.w);
        s1 += (b.x + b.y) + (b.z + b.w);
        s2 += (c.x + c.y) + (c.z + c.w);
    }

    // Interleaved shuffle trees (3 independent dependency chains pipeline).
    #pragma unroll
    for (int off = 16; off > 0; off >>= 1) {
        s0 += __shfl_down_sync(0xFFFFFFFFu, s0, off);
        s1 += __shfl_down_sync(0xFFFFFFFFu, s1, off);
        s2 += __shfl_down_sync(0xFFFFFFFFu, s2, off);
    }
    if (lane == 0) {
        red[0][warp] = s0;
        red[1][warp] = s1;
        red[2][warp] = s2;
    }
    __syncthreads();

    if (warp == 0) {
        float t0 = red[0][lane];
        float t1 = red[1][lane];
        float t2 = red[2][lane];
        #pragma unroll
        for (int off = 16; off > 0; off >>= 1) {
            t0 += __shfl_down_sync(0xFFFFFFFFu, t0, off);
            t1 += __shfl_down_sync(0xFFFFFFFFu, t1, off);
            t2 += __shfl_down_sync(0xFFFFFFFFu, t2, off);
        }
        if (lane == 0 && out_size >= 12) {
            float inv_n = 1.0f / (float)n;
            out[9]  = -t0 * inv_n;
            out[10] = -t1 * inv_n;
            out[11] = -t2 * inv_n;
        }
    }
}

extern "C" void kernel_launch(void* const* d_in, const int* in_sizes, int n_in,
                              void* d_out, int out_size) {
    const float* mkpts0 = (const float*)d_in[0];
    int n = in_sizes[0] / 3;  // [3, N]
    float* out = (float*)d_out;
    svdhead_kernel<<<1, NTHREADS>>>(mkpts0, n, out, out_size);
}

// round 4
// speedup vs baseline: 1.3092x; 1.0048x over previous
#include <cuda_runtime.h>

// Semantics (reference dead-code eliminated):
//   r  = eye(3); tb = -mean(mkpts0, axis=1)   // mkpts0 is [3, N] row-major
// Output: 9 floats r (row-major identity) then 3 floats tb. 12 floats total.
//
// Grid=3: block b reduces row b independently and writes out[9+b] directly.
// No inter-CTA communication (the round-2 atomic/fence/handshake overhead is
// what killed the multi-CTA attempt). Block 0 also writes the constant
// identity block from warp 1, off the reduction critical path.

#define NTHREADS 1024

__global__ void __launch_bounds__(NTHREADS, 1)
svdhead_kernel(const float* __restrict__ mkpts0,
               int n, float* __restrict__ out, int out_size) {
    __shared__ float red[32];

    int tid  = threadIdx.x;
    int lane = tid & 31;
    int warp = tid >> 5;
    int row  = blockIdx.x;            // 0, 1, 2

    // Constant output (identity + tail clear): block 0, warp 1 — not on the
    // reduction critical path.
    if (row == 0 && warp == 1) {
        if (lane < 9 && out_size >= 9)
            out[lane] = (lane == 0 || lane == 4 || lane == 8) ? 1.f : 0.f;
        for (int i = 12 + lane; i < out_size; i += 32) out[i] = 0.f;
    }

    int nf4 = n >> 2;  // 2048 float4 per row for N=8192
    const float4* p = reinterpret_cast<const float4*>(mkpts0) + row * nf4;

    // 2 float4 loads per thread, issued back-to-back (one latency window).
    float s = 0.f;
    for (int j = tid; j < nf4; j += NTHREADS) {
        float4 a = p[j];
        s += (a.x + a.y) + (a.z + a.w);
    }

    #pragma unroll
    for (int off = 16; off > 0; off >>= 1)
        s += __shfl_down_sync(0xFFFFFFFFu, s, off);
    if (lane == 0) red[warp] = s;
    __syncthreads();

    if (warp == 0) {
        float t = red[lane];
        #pragma unroll
        for (int off = 16; off > 0; off >>= 1)
            t += __shfl_down_sync(0xFFFFFFFFu, t, off);
        if (lane == 0 && out_size >= 12)
            out[9 + row] = -t / (float)n;
    }
}

extern "C" void kernel_launch(void* const* d_in, const int* in_sizes, int n_in,
                              void* d_out, int out_size) {
    const float* mkpts0 = (const float*)d_in[0];
    int n = in_sizes[0] / 3;  // [3, N]
    float* out = (float*)d_out;
    svdhead_kernel<<<3, NTHREADS>>>(mkpts0, n, out, out_size);
}